// round 6
// baseline (speedup 1.0000x reference)
#include <cuda_runtime.h>
#include <math.h>

// ---------------------------------------------------------------------------
// N=90000, D=H=128, 2H=256, E=1.44M, G=3000, P=675000.
// ---------------------------------------------------------------------------
#define MAXN 90112
#define MAXG 4096

__device__ float g_agg [MAXN * 128];
__device__ float g_ht  [MAXN * 512];
__device__ float g_h1  [MAXN * 128];
__device__ float g_h2  [MAXN * 128];
__device__ float g_mean[MAXN * 128];
__device__ float g_ls  [MAXN * 128];
__device__ float g_u   [MAXN];
__device__ float g_v   [MAXN];
__device__ float g_colsum[512];
__device__ float g_colsq [512];
__device__ float g_scale [512];
__device__ float g_shift [512];
__device__ float g_pool[MAXG];
__device__ float g_cnt [MAXG];
__device__ float g_acc [2];

__device__ __forceinline__ float f2tf(float f) {
    unsigned r;
    asm("cvt.rna.tf32.f32 %0, %1;" : "=r"(r) : "f"(f));
    return __uint_as_float(r);
}
__device__ __forceinline__ void mma_tf32(float4& d, const float4& a,
                                         float b0, float b1) {
    asm volatile(
        "mma.sync.aligned.m16n8k8.row.col.f32.tf32.tf32.f32 "
        "{%0,%1,%2,%3},{%4,%5,%6,%7},{%8,%9},{%0,%1,%2,%3};"
        : "+f"(d.x), "+f"(d.y), "+f"(d.z), "+f"(d.w)
        : "r"(__float_as_uint(a.x)), "r"(__float_as_uint(a.y)),
          "r"(__float_as_uint(a.z)), "r"(__float_as_uint(a.w)),
          "r"(__float_as_uint(b0)), "r"(__float_as_uint(b1)));
}

// ---------------------------------------------------------------------------
// Edge scatter: agg[dst] += x[src].  One warp per edge, vector red.
// ---------------------------------------------------------------------------
__global__ void scatter_k(const float* __restrict__ X,
                          const int* __restrict__ ei, int E) {
    int gw   = (blockIdx.x * blockDim.x + threadIdx.x) >> 5;
    int lane = threadIdx.x & 31;
    if (gw >= E) return;
    int s = __ldg(ei + gw);
    int d = __ldg(ei + E + gw);
    float4 vv = *(const float4*)(X + (size_t)s * 128 + lane * 4);
    float* dst = g_agg + (size_t)d * 128 + lane * 4;
    asm volatile("red.global.add.v4.f32 [%0], {%1,%2,%3,%4};"
                 :: "l"(dst), "f"(vv.x), "f"(vv.y), "f"(vv.z), "f"(vv.w)
                 : "memory");
}

// ---------------------------------------------------------------------------
// 3xTF32 GEMM, fragment-major smem: each warp-lane's 4 mma fragment regs are
// contiguous 16B -> LDS.128.  128x128 tile, 8 warps (4m x 2n), m16n8k8.
// A tiles: k8 x m16 (16 tiles), B tiles: k8 x n16 (16 tiles), stride 136 fl.
// ---------------------------------------------------------------------------
#define BM 128
#define BN 128
#define BK 16
#define TSF 136                       // tile stride (floats), 544B: 16B-aligned
#define NTILES 16                     // (BK/8) * (BM/16)

// A fragment-major address: value (k in 0..15, m in 0..127)
__device__ __forceinline__ int a_fm_base(int k, int m) {
    int ts = k >> 3, tm = m >> 4;
    int jb = ((k & 4) ? 2 : 0) | ((m & 8) ? 1 : 0);
    return (ts * 8 + tm) * TSF + (m & 7) * 16 + (k & 3) * 4 + jb;
}
// per +1 in k (within quad): lane' += 1 -> +4 floats
// B fragment-major address: value (k in 0..15, n in 0..127)
__device__ __forceinline__ int b_fm_base(int k, int n) {
    int ts = k >> 3, tn = n >> 4;
    int jb = ((k & 4) ? 1 : 0) | ((n & 8) ? 2 : 0);
    return (ts * 8 + tn) * TSF + (n & 7) * 16 + (k & 3) * 4 + jb;
}

#define MMA3(ACC, AH, AL, BH0, BH1, BL0, BL1)  \
    do { mma_tf32(ACC, AH, BH0, BH1);          \
         mma_tf32(ACC, AL, BH0, BH1);          \
         mma_tf32(ACC, AH, BL0, BL1); } while (0)

// GEMM1: OUT[:, n0:n0+128] = (X+agg) @ W + bias ; fused colsum/colsq stats.
__global__ void __launch_bounds__(256) gemm1_k(
    const float* __restrict__ X, const float* __restrict__ Wa,
    const float* __restrict__ Wb, const float* __restrict__ bias,
    float* __restrict__ OUT, int N, int ldo) {
    __shared__ __align__(16) float Ahf[NTILES * TSF], Alf[NTILES * TSF];
    __shared__ __align__(16) float Bhf[NTILES * TSF], Blf[NTILES * TSF];
    int tid  = threadIdx.x;
    int row0 = blockIdx.y * BM;
    int n0   = blockIdx.x * BN;
    const float* W = (n0 < 256) ? Wa : Wb;
    int nbase = (n0 < 256) ? n0 : (n0 - 256);
    int lane = tid & 31, wid = tid >> 5;
    int lk = lane & 3, lm = lane >> 2;
    int warpM = wid & 3, warpN = wid >> 2;
    int mBase = warpM * 32, nBase = warpN * 64;
    float4 acc[2][8];
    #pragma unroll
    for (int i = 0; i < 2; i++)
        #pragma unroll
        for (int j = 0; j < 8; j++) acc[i][j] = make_float4(0.f,0.f,0.f,0.f);

    for (int kk = 0; kk < 128; kk += BK) {
        #pragma unroll
        for (int h = 0; h < 2; h++) {
            int idx = h * 256 + tid;
            int m = idx & 127, k = (idx >> 7) * 4;
            int rg = row0 + m;
            float4 a = make_float4(0.f,0.f,0.f,0.f);
            if (rg < N) {
                size_t off = (size_t)rg * 128 + kk + k;
                float4 xv = *(const float4*)(X + off);
                float4 av = *(const float4*)(g_agg + off);
                a.x = xv.x + av.x; a.y = xv.y + av.y;
                a.z = xv.z + av.z; a.w = xv.w + av.w;
            }
            int ab = a_fm_base(k, m);
            float h0 = f2tf(a.x), h1 = f2tf(a.y), h2 = f2tf(a.z), h3 = f2tf(a.w);
            Ahf[ab]      = h0; Alf[ab]      = f2tf(a.x - h0);
            Ahf[ab + 4]  = h1; Alf[ab + 4]  = f2tf(a.y - h1);
            Ahf[ab + 8]  = h2; Alf[ab + 8]  = f2tf(a.z - h2);
            Ahf[ab + 12] = h3; Alf[ab + 12] = f2tf(a.w - h3);
            int kb = idx >> 5, nc = (idx & 31) * 4;
            float4 w4 = *(const float4*)(W + (size_t)(kk + kb) * 256 + nbase + nc);
            int bb = b_fm_base(kb, nc);
            float g0 = f2tf(w4.x), g1 = f2tf(w4.y), g2 = f2tf(w4.z), g3 = f2tf(w4.w);
            Bhf[bb]      = g0; Blf[bb]      = f2tf(w4.x - g0);
            Bhf[bb + 16] = g1; Blf[bb + 16] = f2tf(w4.y - g1);
            Bhf[bb + 32] = g2; Blf[bb + 32] = f2tf(w4.z - g2);
            Bhf[bb + 48] = g3; Blf[bb + 48] = f2tf(w4.w - g3);
        }
        __syncthreads();
        #pragma unroll
        for (int s = 0; s < 2; s++) {
            float4 ah[2], al[2];
            #pragma unroll
            for (int wm = 0; wm < 2; wm++) {
                int t = (s * 8 + warpM * 2 + wm) * TSF;
                ah[wm] = ((const float4*)(Ahf + t))[lane];
                al[wm] = ((const float4*)(Alf + t))[lane];
            }
            #pragma unroll
            for (int wp = 0; wp < 4; wp++) {
                int t = (s * 8 + warpN * 4 + wp) * TSF;
                float4 bh = ((const float4*)(Bhf + t))[lane];
                float4 bl = ((const float4*)(Blf + t))[lane];
                #pragma unroll
                for (int wm = 0; wm < 2; wm++) {
                    MMA3(acc[wm][2*wp],   ah[wm], al[wm], bh.x, bh.y, bl.x, bl.y);
                    MMA3(acc[wm][2*wp+1], ah[wm], al[wm], bh.z, bh.w, bl.z, bl.w);
                }
            }
        }
        __syncthreads();
    }

    // epilogue: bias, store, per-column stats
    float psx[8]={}, psy[8]={}, pqx[8]={}, pqy[8]={};
    #pragma unroll
    for (int wn = 0; wn < 8; wn++) {
        int col = n0 + nBase + wn * 8 + 2 * lk;
        float bx = bias[col], by = bias[col + 1];
        #pragma unroll
        for (int wm = 0; wm < 2; wm++) {
            float4 d = acc[wm][wn];
            int ra = row0 + mBase + wm * 16 + lm;
            int rb = ra + 8;
            float ox = d.x + bx, oy = d.y + by;
            float oz = d.z + bx, ow = d.w + by;
            if (ra < N) {
                *(float2*)(OUT + (size_t)ra * ldo + col) = make_float2(ox, oy);
                psx[wn] += ox; psy[wn] += oy;
                pqx[wn] += ox * ox; pqy[wn] += oy * oy;
            }
            if (rb < N) {
                *(float2*)(OUT + (size_t)rb * ldo + col) = make_float2(oz, ow);
                psx[wn] += oz; psy[wn] += ow;
                pqx[wn] += oz * oz; pqy[wn] += ow * ow;
            }
        }
    }
    #pragma unroll
    for (int wn = 0; wn < 8; wn++) {
        #pragma unroll
        for (int o = 4; o <= 16; o <<= 1) {
            psx[wn] += __shfl_xor_sync(0xffffffffu, psx[wn], o);
            psy[wn] += __shfl_xor_sync(0xffffffffu, psy[wn], o);
            pqx[wn] += __shfl_xor_sync(0xffffffffu, pqx[wn], o);
            pqy[wn] += __shfl_xor_sync(0xffffffffu, pqy[wn], o);
        }
    }
    if (lane < 4) {
        #pragma unroll
        for (int wn = 0; wn < 8; wn++) {
            int col = n0 + nBase + wn * 8 + 2 * lane;
            atomicAdd(&g_colsum[col],     psx[wn]);
            atomicAdd(&g_colsum[col + 1], psy[wn]);
            atomicAdd(&g_colsq[col],      pqx[wn]);
            atomicAdd(&g_colsq[col + 1],  pqy[wn]);
        }
    }
}

__global__ void bnfin_k(const float* __restrict__ gamma,
                        const float* __restrict__ beta, int N) {
    int c = blockIdx.x * blockDim.x + threadIdx.x;
    float invN = 1.0f / (float)N;
    float mu  = g_colsum[c] * invN;
    float var = g_colsq[c] * invN - mu * mu;
    float sc  = gamma[c] * rsqrtf(var + 1e-5f);
    g_scale[c] = sc;
    g_shift[c] = beta[c] - mu * sc;
}

// GEMM2: OUT[N,128] = BN(HT[:,koff:koff+256]) [relu] @ W[256,128] + b2
__global__ void __launch_bounds__(256) gemm2_k(
    const float* __restrict__ HT, const float* __restrict__ W,
    const float* __restrict__ bias, float* __restrict__ OUT,
    int N, int ldh, int koff, int relu) {
    __shared__ __align__(16) float Ahf[NTILES * TSF], Alf[NTILES * TSF];
    __shared__ __align__(16) float Bhf[NTILES * TSF], Blf[NTILES * TSF];
    int tid  = threadIdx.x;
    int row0 = blockIdx.y * BM;
    int n0   = blockIdx.x * BN;
    int lane = tid & 31, wid = tid >> 5;
    int lk = lane & 3, lm = lane >> 2;
    int warpM = wid & 3, warpN = wid >> 2;
    int mBase = warpM * 32, nBase = warpN * 64;
    float4 acc[2][8];
    #pragma unroll
    for (int i = 0; i < 2; i++)
        #pragma unroll
        for (int j = 0; j < 8; j++) acc[i][j] = make_float4(0.f,0.f,0.f,0.f);

    for (int kk = 0; kk < 256; kk += BK) {
        #pragma unroll
        for (int h = 0; h < 2; h++) {
            int idx = h * 256 + tid;
            int m = idx & 127, k = (idx >> 7) * 4;
            int rg = row0 + m;
            float4 a = make_float4(0.f,0.f,0.f,0.f);
            if (rg < N) {
                float4 h4 = *(const float4*)(HT + (size_t)rg * ldh + koff + kk + k);
                float4 sc4 = *(const float4*)(g_scale + koff + kk + k);
                float4 sh4 = *(const float4*)(g_shift + koff + kk + k);
                a.x = h4.x * sc4.x + sh4.x;
                a.y = h4.y * sc4.y + sh4.y;
                a.z = h4.z * sc4.z + sh4.z;
                a.w = h4.w * sc4.w + sh4.w;
                if (relu) {
                    a.x = fmaxf(a.x, 0.f); a.y = fmaxf(a.y, 0.f);
                    a.z = fmaxf(a.z, 0.f); a.w = fmaxf(a.w, 0.f);
                }
            }
            int ab = a_fm_base(k, m);
            float h0 = f2tf(a.x), h1 = f2tf(a.y), h2 = f2tf(a.z), h3 = f2tf(a.w);
            Ahf[ab]      = h0; Alf[ab]      = f2tf(a.x - h0);
            Ahf[ab + 4]  = h1; Alf[ab + 4]  = f2tf(a.y - h1);
            Ahf[ab + 8]  = h2; Alf[ab + 8]  = f2tf(a.z - h2);
            Ahf[ab + 12] = h3; Alf[ab + 12] = f2tf(a.w - h3);
            int kb = idx >> 5, nc = (idx & 31) * 4;
            float4 w4 = *(const float4*)(W + (size_t)(kk + kb) * 128 + n0 + nc);
            int bb = b_fm_base(kb, nc);
            float g0 = f2tf(w4.x), g1 = f2tf(w4.y), g2 = f2tf(w4.z), g3 = f2tf(w4.w);
            Bhf[bb]      = g0; Blf[bb]      = f2tf(w4.x - g0);
            Bhf[bb + 16] = g1; Blf[bb + 16] = f2tf(w4.y - g1);
            Bhf[bb + 32] = g2; Blf[bb + 32] = f2tf(w4.z - g2);
            Bhf[bb + 48] = g3; Blf[bb + 48] = f2tf(w4.w - g3);
        }
        __syncthreads();
        #pragma unroll
        for (int s = 0; s < 2; s++) {
            float4 ah[2], al[2];
            #pragma unroll
            for (int wm = 0; wm < 2; wm++) {
                int t = (s * 8 + warpM * 2 + wm) * TSF;
                ah[wm] = ((const float4*)(Ahf + t))[lane];
                al[wm] = ((const float4*)(Alf + t))[lane];
            }
            #pragma unroll
            for (int wp = 0; wp < 4; wp++) {
                int t = (s * 8 + warpN * 4 + wp) * TSF;
                float4 bh = ((const float4*)(Bhf + t))[lane];
                float4 bl = ((const float4*)(Blf + t))[lane];
                #pragma unroll
                for (int wm = 0; wm < 2; wm++) {
                    MMA3(acc[wm][2*wp],   ah[wm], al[wm], bh.x, bh.y, bl.x, bl.y);
                    MMA3(acc[wm][2*wp+1], ah[wm], al[wm], bh.z, bh.w, bl.z, bl.w);
                }
            }
        }
        __syncthreads();
    }

    #pragma unroll
    for (int wn = 0; wn < 8; wn++) {
        int col = n0 + nBase + wn * 8 + 2 * lk;
        float bx = bias[col], by = bias[col + 1];
        #pragma unroll
        for (int wm = 0; wm < 2; wm++) {
            float4 d = acc[wm][wn];
            int ra = row0 + mBase + wm * 16 + lm;
            int rb = ra + 8;
            if (ra < N)
                *(float2*)(OUT + (size_t)ra * 128 + col) = make_float2(d.x + bx, d.y + by);
            if (rb < N)
                *(float2*)(OUT + (size_t)rb * 128 + col) = make_float2(d.z + bx, d.w + by);
        }
    }
}

// ---------------------------------------------------------------------------
// z epilogue and small kernels.
// ---------------------------------------------------------------------------
__global__ void z_k(const float* __restrict__ MEAN, const float* __restrict__ LS,
                    const float* __restrict__ NOISE, const int* __restrict__ batch,
                    const float* __restrict__ Wn, const float* __restrict__ Wc,
                    int N) {
    __shared__ float klred[8];
    int lane = threadIdx.x & 31;
    int w    = threadIdx.x >> 5;
    int row  = blockIdx.x * 8 + w;
    float klp = 0.f;
    if (row < N) {
        size_t off = (size_t)row * 128 + lane * 4;
        float4 m4 = *(const float4*)(MEAN + off);
        float4 l4 = *(const float4*)(LS + off);
        float4 n4 = *(const float4*)(NOISE + off);
        float4 e4 = make_float4(expf(l4.x), expf(l4.y), expf(l4.z), expf(l4.w));
        float4 z4 = make_float4(n4.x * e4.x + m4.x, n4.y * e4.y + m4.y,
                                n4.z * e4.z + m4.z, n4.w * e4.w + m4.w);
        float4 wa = *(const float4*)(Wc + lane * 4);
        float4 wb = *(const float4*)(Wc + 128 + lane * 4);
        float4 wn = *(const float4*)(Wn + lane * 4);
        float up = z4.x * wa.x + z4.y * wa.y + z4.z * wa.z + z4.w * wa.w;
        float vp = z4.x * wb.x + z4.y * wb.y + z4.z * wb.z + z4.w * wb.w;
        float sp = z4.x * wn.x + z4.y * wn.y + z4.z * wn.z + z4.w * wn.w;
        klp = (1.f + 2.f * l4.x - m4.x * m4.x - e4.x * e4.x)
            + (1.f + 2.f * l4.y - m4.y * m4.y - e4.y * e4.y)
            + (1.f + 2.f * l4.z - m4.z * m4.z - e4.z * e4.z)
            + (1.f + 2.f * l4.w - m4.w * m4.w - e4.w * e4.w);
        #pragma unroll
        for (int o = 16; o > 0; o >>= 1) {
            up  += __shfl_xor_sync(0xffffffffu, up,  o);
            vp  += __shfl_xor_sync(0xffffffffu, vp,  o);
            sp  += __shfl_xor_sync(0xffffffffu, sp,  o);
            klp += __shfl_xor_sync(0xffffffffu, klp, o);
        }
        if (lane == 0) {
            g_u[row] = up;
            g_v[row] = vp;
            int b = batch[row];
            atomicAdd(&g_pool[b], sp);
            atomicAdd(&g_cnt[b], 1.0f);
        }
    }
    if (lane == 0) klred[w] = (row < N) ? klp : 0.f;
    __syncthreads();
    if (threadIdx.x == 0) {
        float t = 0.f;
        #pragma unroll
        for (int i = 0; i < 8; i++) t += klred[i];
        atomicAdd(&g_acc[0], t);
    }
}

__global__ void num_k(const float* __restrict__ bridge_num,
                      const float* __restrict__ bnp,
                      float* __restrict__ out_np, int G) {
    __shared__ float red[256];
    int g = blockIdx.x * 256 + threadIdx.x;
    float d = 0.f;
    if (g < G) {
        float np = g_pool[g] / g_cnt[g] + bnp[0];
        out_np[g] = np;
        d = fabsf(np - bridge_num[g]);
    }
    red[threadIdx.x] = d;
    __syncthreads();
    for (int s = 128; s > 0; s >>= 1) {
        if (threadIdx.x < s) red[threadIdx.x] += red[threadIdx.x + s];
        __syncthreads();
    }
    if (threadIdx.x == 0) atomicAdd(&g_acc[1], red[0]);
}

__global__ void apred_k(const int* __restrict__ bidx,
                        const float* __restrict__ bcp,
                        float* __restrict__ out, int P) {
    int p = blockIdx.x * 256 + threadIdx.x;
    if (p >= P) return;
    int i = __ldg(bidx + p);
    int j = __ldg(bidx + P + p);
    float logit = g_u[i] + g_v[j] + bcp[0];
    out[p] = 1.0f / (1.0f + expf(-logit));
}

__global__ void fin_k(float* __restrict__ out, int P, int N, int G) {
    out[P]     = 0.5f * g_acc[0] / ((float)N * (float)N);
    out[P + 1] = g_acc[1] / (float)G;
}

// ---------------------------------------------------------------------------
// Launcher
// ---------------------------------------------------------------------------
extern "C" void kernel_launch(void* const* d_in, const int* in_sizes, int n_in,
                              void* d_out, int out_size) {
    const float* x          = (const float*)d_in[0];
    const int*   ei         = (const int*)  d_in[1];
    const int*   batch      = (const int*)  d_in[2];
    const float* bridge_num = (const float*)d_in[3];
    const int*   bidx       = (const int*)  d_in[4];
    const float* noise      = (const float*)d_in[5];
    const float* W1s        = (const float*)d_in[6];
    const float* b1s        = (const float*)d_in[7];
    const float* gammas     = (const float*)d_in[8];
    const float* betas      = (const float*)d_in[9];
    const float* W2s        = (const float*)d_in[10];
    const float* b2s        = (const float*)d_in[11];
    const float* Wn         = (const float*)d_in[12];
    const float* bnp        = (const float*)d_in[13];
    const float* Wc         = (const float*)d_in[14];
    const float* bcp        = (const float*)d_in[15];
    float* out = (float*)d_out;

    int N = in_sizes[0] / 128;
    int E = in_sizes[1] / 2;
    int G = in_sizes[3];
    int P = in_sizes[4] / 2;

    float *agg, *ht, *h1, *h2, *mean, *ls, *colsum, *colsq, *pool, *cnt, *acc;
    cudaGetSymbolAddress((void**)&agg,    g_agg);
    cudaGetSymbolAddress((void**)&ht,     g_ht);
    cudaGetSymbolAddress((void**)&h1,     g_h1);
    cudaGetSymbolAddress((void**)&h2,     g_h2);
    cudaGetSymbolAddress((void**)&mean,   g_mean);
    cudaGetSymbolAddress((void**)&ls,     g_ls);
    cudaGetSymbolAddress((void**)&colsum, g_colsum);
    cudaGetSymbolAddress((void**)&colsq,  g_colsq);
    cudaGetSymbolAddress((void**)&pool,   g_pool);
    cudaGetSymbolAddress((void**)&cnt,    g_cnt);
    cudaGetSymbolAddress((void**)&acc,    g_acc);

    int rb = (N + BM - 1) / BM;
    int scat_blocks = (E * 32 + 511) / 512;

    // ---- layer 0 ----
    cudaMemsetAsync(agg, 0, (size_t)N * 128 * sizeof(float));
    scatter_k<<<scat_blocks, 512>>>(x, ei, E);
    cudaMemsetAsync(colsum, 0, 512 * sizeof(float));
    cudaMemsetAsync(colsq,  0, 512 * sizeof(float));
    gemm1_k<<<dim3(2, rb), 256>>>(x, W1s, W1s, b1s, ht, N, 256);
    bnfin_k<<<1, 256>>>(gammas, betas, N);
    gemm2_k<<<dim3(1, rb), 256>>>(ht, W2s, b2s, h1, N, 256, 0, 1);

    // ---- layer 1 ----
    cudaMemsetAsync(agg, 0, (size_t)N * 128 * sizeof(float));
    scatter_k<<<scat_blocks, 512>>>(h1, ei, E);
    cudaMemsetAsync(colsum, 0, 512 * sizeof(float));
    cudaMemsetAsync(colsq,  0, 512 * sizeof(float));
    gemm1_k<<<dim3(2, rb), 256>>>(h1, W1s + 1 * 128 * 256, W1s, b1s + 256, ht, N, 256);
    bnfin_k<<<1, 256>>>(gammas + 256, betas + 256, N);
    gemm2_k<<<dim3(1, rb), 256>>>(ht, W2s + 1 * 256 * 128, b2s + 128, h2, N, 256, 0, 1);

    // ---- layers 2+3 combined (shared A = h2 + agg(h2)) ----
    cudaMemsetAsync(agg, 0, (size_t)N * 128 * sizeof(float));
    scatter_k<<<scat_blocks, 512>>>(h2, ei, E);
    cudaMemsetAsync(colsum, 0, 512 * sizeof(float));
    cudaMemsetAsync(colsq,  0, 512 * sizeof(float));
    gemm1_k<<<dim3(4, rb), 256>>>(h2, W1s + 2 * 128 * 256, W1s + 3 * 128 * 256,
                                  b1s + 512, ht, N, 512);
    bnfin_k<<<1, 512>>>(gammas + 512, betas + 512, N);
    gemm2_k<<<dim3(1, rb), 256>>>(ht, W2s + 2 * 256 * 128, b2s + 256, mean, N, 512, 0,   0);
    gemm2_k<<<dim3(1, rb), 256>>>(ht, W2s + 3 * 256 * 128, b2s + 384, ls,   N, 512, 256, 0);

    // ---- epilogue ----
    cudaMemsetAsync(pool, 0, G * sizeof(float));
    cudaMemsetAsync(cnt,  0, G * sizeof(float));
    cudaMemsetAsync(acc,  0, 2 * sizeof(float));
    z_k<<<(N + 7) / 8, 256>>>(mean, ls, noise, batch, Wn, Wc, N);
    num_k<<<(G + 255) / 256, 256>>>(bridge_num, bnp, out + P + 2, G);
    apred_k<<<(P + 255) / 256, 256>>>(bidx, bcp, out, P);
    fin_k<<<1, 1>>>(out, P, N, G);
}

// round 8
// speedup vs baseline: 1.2187x; 1.2187x over previous
#include <cuda_runtime.h>
#include <cuda_bf16.h>
#include <math.h>

// ---------------------------------------------------------------------------
// N=90000, D=H=128, 2H=256, E=1.44M, G=3000, P=675000.
// ---------------------------------------------------------------------------
#define MAXN 90112
#define MAXG 4096

__device__ float g_agg [MAXN * 128];
__device__ float g_ht  [MAXN * 512];
__device__ float g_h1  [MAXN * 128];
__device__ float g_h2  [MAXN * 128];
__device__ float g_mean[MAXN * 128];
__device__ float g_ls  [MAXN * 128];
__device__ float g_u   [MAXN];
__device__ float g_v   [MAXN];
__device__ float g_colsum[512];
__device__ float g_colsq [512];
__device__ float g_scale [512];
__device__ float g_shift [512];
__device__ float g_pool[MAXG];
__device__ float g_cnt [MAXG];
__device__ float g_acc [2];

// ---------------------------------------------------------------------------
// bf16 helpers: hi/lo split words (two k-adjacent bf16 packed per uint32).
// ---------------------------------------------------------------------------
__device__ __forceinline__ void bfsplit2(float e0, float e1,
                                         unsigned& wh, unsigned& wl) {
    __nv_bfloat16 h0 = __float2bfloat16_rn(e0);
    __nv_bfloat16 h1 = __float2bfloat16_rn(e1);
    __nv_bfloat16 l0 = __float2bfloat16_rn(e0 - __bfloat162float(h0));
    __nv_bfloat16 l1 = __float2bfloat16_rn(e1 - __bfloat162float(h1));
    __nv_bfloat162 vh = __nv_bfloat162(h0, h1);   // .x = low half-word
    __nv_bfloat162 vl = __nv_bfloat162(l0, l1);
    wh = *(unsigned*)&vh;
    wl = *(unsigned*)&vl;
}

__device__ __forceinline__ void mma_bf16(float4& d, const unsigned* a,
                                         unsigned b0, unsigned b1) {
    asm volatile(
        "mma.sync.aligned.m16n8k16.row.col.f32.bf16.bf16.f32 "
        "{%0,%1,%2,%3},{%4,%5,%6,%7},{%8,%9},{%0,%1,%2,%3};"
        : "+f"(d.x), "+f"(d.y), "+f"(d.z), "+f"(d.w)
        : "r"(a[0]), "r"(a[1]), "r"(a[2]), "r"(a[3]), "r"(b0), "r"(b1));
}

// ---------------------------------------------------------------------------
// Edge scatter: agg[dst] += x[src].  One warp per edge, vector red.
// ---------------------------------------------------------------------------
__global__ void scatter_k(const float* __restrict__ X,
                          const int* __restrict__ ei, int E) {
    int gw   = (blockIdx.x * blockDim.x + threadIdx.x) >> 5;
    int lane = threadIdx.x & 31;
    if (gw >= E) return;
    int s = __ldg(ei + gw);
    int d = __ldg(ei + E + gw);
    float4 vv = *(const float4*)(X + (size_t)s * 128 + lane * 4);
    float* dst = g_agg + (size_t)d * 128 + lane * 4;
    asm volatile("red.global.add.v4.f32 [%0], {%1,%2,%3,%4};"
                 :: "l"(dst), "f"(vv.x), "f"(vv.y), "f"(vv.z), "f"(vv.w)
                 : "memory");
}

// ---------------------------------------------------------------------------
// bf16x3 tensor GEMM: 128x128 tile, 8 warps (4m x 2n), warp 32x64, m16n8k16.
// Smem words: [k2][m] / [k2][n], k2 = k/2 (bf16 pair per word), stride 136.
// Loads AND stores provably bank-conflict-free.
// ---------------------------------------------------------------------------
#define BM 128
#define BN 128
#define BK 16
#define KW 136     // word stride per k2-row

#define MMA3(ACC, AH, AL, BH0, BH1, BL0, BL1)  \
    do { mma_bf16(ACC, AH, BH0, BH1);          \
         mma_bf16(ACC, AL, BH0, BH1);          \
         mma_bf16(ACC, AH, BL0, BL1); } while (0)

// GEMM1: OUT[:, n0:n0+128] = (X+agg) @ W + bias ; fused colsum/colsq stats.
__global__ void __launch_bounds__(256) gemm1_k(
    const float* __restrict__ X, const float* __restrict__ Wa,
    const float* __restrict__ Wb, const float* __restrict__ bias,
    float* __restrict__ OUT, int N, int ldo) {
    __shared__ unsigned Ah[8 * KW], Al[8 * KW];
    __shared__ unsigned Bh[8 * KW], Bl[8 * KW];
    int tid  = threadIdx.x;
    int row0 = blockIdx.y * BM;
    int n0   = blockIdx.x * BN;
    const float* W = (n0 < 256) ? Wa : Wb;
    int nbase = (n0 < 256) ? n0 : (n0 - 256);
    int lane = tid & 31, wid = tid >> 5;
    int lk = lane & 3, lm = lane >> 2;
    int warpM = wid & 3, warpN = wid >> 2;
    int mBase = warpM * 32, nBase = warpN * 64;
    float4 acc[2][8];
    #pragma unroll
    for (int i = 0; i < 2; i++)
        #pragma unroll
        for (int j = 0; j < 8; j++) acc[i][j] = make_float4(0.f,0.f,0.f,0.f);

    for (int kk = 0; kk < 128; kk += BK) {
        #pragma unroll
        for (int h = 0; h < 2; h++) {
            int idx = h * 256 + tid;
            int m  = idx & 127;
            int kq = (idx >> 7) * 4;          // 0,4 (h=0) / 8,12 (h=1)
            int rg = row0 + m;
            float4 a = make_float4(0.f,0.f,0.f,0.f);
            if (rg < N) {
                size_t off = (size_t)rg * 128 + kk + kq;
                float4 xv = *(const float4*)(X + off);
                float4 av = *(const float4*)(g_agg + off);
                a.x = xv.x + av.x; a.y = xv.y + av.y;
                a.z = xv.z + av.z; a.w = xv.w + av.w;
            }
            unsigned wh0, wl0, wh1, wl1;
            bfsplit2(a.x, a.y, wh0, wl0);
            bfsplit2(a.z, a.w, wh1, wl1);
            int aw = (kq >> 1) * KW + m;
            Ah[aw] = wh0; Al[aw] = wl0;
            Ah[aw + KW] = wh1; Al[aw + KW] = wl1;
            // B: same (n, kq) mapping; 4 coalesced scalar loads along k
            const float* wp = W + (size_t)(kk + kq) * 256 + nbase + m;
            float b0 = wp[0], b1 = wp[256], b2 = wp[512], b3 = wp[768];
            bfsplit2(b0, b1, wh0, wl0);
            bfsplit2(b2, b3, wh1, wl1);
            Bh[aw] = wh0; Bl[aw] = wl0;
            Bh[aw + KW] = wh1; Bl[aw + KW] = wl1;
        }
        __syncthreads();
        unsigned ah[2][4], al[2][4];
        #pragma unroll
        for (int wm = 0; wm < 2; wm++) {
            int mr = mBase + wm * 16 + lm;
            ah[wm][0] = Ah[lk * KW + mr];
            ah[wm][1] = Ah[lk * KW + mr + 8];
            ah[wm][2] = Ah[(lk + 4) * KW + mr];
            ah[wm][3] = Ah[(lk + 4) * KW + mr + 8];
            al[wm][0] = Al[lk * KW + mr];
            al[wm][1] = Al[lk * KW + mr + 8];
            al[wm][2] = Al[(lk + 4) * KW + mr];
            al[wm][3] = Al[(lk + 4) * KW + mr + 8];
        }
        #pragma unroll
        for (int wn = 0; wn < 8; wn++) {
            int nc = nBase + wn * 8 + lm;
            unsigned bh0 = Bh[lk * KW + nc], bh1 = Bh[(lk + 4) * KW + nc];
            unsigned bl0 = Bl[lk * KW + nc], bl1 = Bl[(lk + 4) * KW + nc];
            #pragma unroll
            for (int wm = 0; wm < 2; wm++)
                MMA3(acc[wm][wn], ah[wm], al[wm], bh0, bh1, bl0, bl1);
        }
        __syncthreads();
    }

    // epilogue: bias, store, per-column stats
    float psx[8]={}, psy[8]={}, pqx[8]={}, pqy[8]={};
    #pragma unroll
    for (int wn = 0; wn < 8; wn++) {
        int col = n0 + nBase + wn * 8 + 2 * lk;
        float bx = bias[col], by = bias[col + 1];
        #pragma unroll
        for (int wm = 0; wm < 2; wm++) {
            float4 d = acc[wm][wn];
            int ra = row0 + mBase + wm * 16 + lm;
            int rb = ra + 8;
            float ox = d.x + bx, oy = d.y + by;
            float oz = d.z + bx, ow = d.w + by;
            if (ra < N) {
                *(float2*)(OUT + (size_t)ra * ldo + col) = make_float2(ox, oy);
                psx[wn] += ox; psy[wn] += oy;
                pqx[wn] += ox * ox; pqy[wn] += oy * oy;
            }
            if (rb < N) {
                *(float2*)(OUT + (size_t)rb * ldo + col) = make_float2(oz, ow);
                psx[wn] += oz; psy[wn] += ow;
                pqx[wn] += oz * oz; pqy[wn] += ow * ow;
            }
        }
    }
    #pragma unroll
    for (int wn = 0; wn < 8; wn++) {
        #pragma unroll
        for (int o = 4; o <= 16; o <<= 1) {
            psx[wn] += __shfl_xor_sync(0xffffffffu, psx[wn], o);
            psy[wn] += __shfl_xor_sync(0xffffffffu, psy[wn], o);
            pqx[wn] += __shfl_xor_sync(0xffffffffu, pqx[wn], o);
            pqy[wn] += __shfl_xor_sync(0xffffffffu, pqy[wn], o);
        }
    }
    if (lane < 4) {
        #pragma unroll
        for (int wn = 0; wn < 8; wn++) {
            int col = n0 + nBase + wn * 8 + 2 * lane;
            atomicAdd(&g_colsum[col],     psx[wn]);
            atomicAdd(&g_colsum[col + 1], psy[wn]);
            atomicAdd(&g_colsq[col],      pqx[wn]);
            atomicAdd(&g_colsq[col + 1],  pqy[wn]);
        }
    }
}

__global__ void bnfin_k(const float* __restrict__ gamma,
                        const float* __restrict__ beta, int N) {
    int c = blockIdx.x * blockDim.x + threadIdx.x;
    float invN = 1.0f / (float)N;
    float mu  = g_colsum[c] * invN;
    float var = g_colsq[c] * invN - mu * mu;
    float sc  = gamma[c] * rsqrtf(var + 1e-5f);
    g_scale[c] = sc;
    g_shift[c] = beta[c] - mu * sc;
}

// GEMM2: OUT[N,128] = BN(HT[:,koff:koff+256]) [relu] @ W[256,128] + b2
__global__ void __launch_bounds__(256) gemm2_k(
    const float* __restrict__ HT, const float* __restrict__ W,
    const float* __restrict__ bias, float* __restrict__ OUT,
    int N, int ldh, int koff, int relu) {
    __shared__ unsigned Ah[8 * KW], Al[8 * KW];
    __shared__ unsigned Bh[8 * KW], Bl[8 * KW];
    int tid  = threadIdx.x;
    int row0 = blockIdx.y * BM;
    int n0   = blockIdx.x * BN;
    int lane = tid & 31, wid = tid >> 5;
    int lk = lane & 3, lm = lane >> 2;
    int warpM = wid & 3, warpN = wid >> 2;
    int mBase = warpM * 32, nBase = warpN * 64;
    float4 acc[2][8];
    #pragma unroll
    for (int i = 0; i < 2; i++)
        #pragma unroll
        for (int j = 0; j < 8; j++) acc[i][j] = make_float4(0.f,0.f,0.f,0.f);

    for (int kk = 0; kk < 256; kk += BK) {
        #pragma unroll
        for (int h = 0; h < 2; h++) {
            int idx = h * 256 + tid;
            int m  = idx & 127;
            int kq = (idx >> 7) * 4;
            int rg = row0 + m;
            float4 a = make_float4(0.f,0.f,0.f,0.f);
            if (rg < N) {
                float4 h4 = *(const float4*)(HT + (size_t)rg * ldh + koff + kk + kq);
                float4 sc4 = *(const float4*)(g_scale + koff + kk + kq);
                float4 sh4 = *(const float4*)(g_shift + koff + kk + kq);
                a.x = h4.x * sc4.x + sh4.x;
                a.y = h4.y * sc4.y + sh4.y;
                a.z = h4.z * sc4.z + sh4.z;
                a.w = h4.w * sc4.w + sh4.w;
                if (relu) {
                    a.x = fmaxf(a.x, 0.f); a.y = fmaxf(a.y, 0.f);
                    a.z = fmaxf(a.z, 0.f); a.w = fmaxf(a.w, 0.f);
                }
            }
            unsigned wh0, wl0, wh1, wl1;
            bfsplit2(a.x, a.y, wh0, wl0);
            bfsplit2(a.z, a.w, wh1, wl1);
            int aw = (kq >> 1) * KW + m;
            Ah[aw] = wh0; Al[aw] = wl0;
            Ah[aw + KW] = wh1; Al[aw + KW] = wl1;
            const float* wp = W + (size_t)(kk + kq) * 128 + n0 + m;
            float b0 = wp[0], b1 = wp[128], b2 = wp[256], b3 = wp[384];
            bfsplit2(b0, b1, wh0, wl0);
            bfsplit2(b2, b3, wh1, wl1);
            Bh[aw] = wh0; Bl[aw] = wl0;
            Bh[aw + KW] = wh1; Bl[aw + KW] = wl1;
        }
        __syncthreads();
        unsigned ah[2][4], al[2][4];
        #pragma unroll
        for (int wm = 0; wm < 2; wm++) {
            int mr = mBase + wm * 16 + lm;
            ah[wm][0] = Ah[lk * KW + mr];
            ah[wm][1] = Ah[lk * KW + mr + 8];
            ah[wm][2] = Ah[(lk + 4) * KW + mr];
            ah[wm][3] = Ah[(lk + 4) * KW + mr + 8];
            al[wm][0] = Al[lk * KW + mr];
            al[wm][1] = Al[lk * KW + mr + 8];
            al[wm][2] = Al[(lk + 4) * KW + mr];
            al[wm][3] = Al[(lk + 4) * KW + mr + 8];
        }
        #pragma unroll
        for (int wn = 0; wn < 8; wn++) {
            int nc = nBase + wn * 8 + lm;
            unsigned bh0 = Bh[lk * KW + nc], bh1 = Bh[(lk + 4) * KW + nc];
            unsigned bl0 = Bl[lk * KW + nc], bl1 = Bl[(lk + 4) * KW + nc];
            #pragma unroll
            for (int wm = 0; wm < 2; wm++)
                MMA3(acc[wm][wn], ah[wm], al[wm], bh0, bh1, bl0, bl1);
        }
        __syncthreads();
    }

    #pragma unroll
    for (int wn = 0; wn < 8; wn++) {
        int col = n0 + nBase + wn * 8 + 2 * lk;
        float bx = bias[col], by = bias[col + 1];
        #pragma unroll
        for (int wm = 0; wm < 2; wm++) {
            float4 d = acc[wm][wn];
            int ra = row0 + mBase + wm * 16 + lm;
            int rb = ra + 8;
            if (ra < N)
                *(float2*)(OUT + (size_t)ra * 128 + col) = make_float2(d.x + bx, d.y + by);
            if (rb < N)
                *(float2*)(OUT + (size_t)rb * 128 + col) = make_float2(d.z + bx, d.w + by);
        }
    }
}

// ---------------------------------------------------------------------------
// z epilogue and small kernels.
// ---------------------------------------------------------------------------
__global__ void z_k(const float* __restrict__ MEAN, const float* __restrict__ LS,
                    const float* __restrict__ NOISE, const int* __restrict__ batch,
                    const float* __restrict__ Wn, const float* __restrict__ Wc,
                    int N) {
    __shared__ float klred[8];
    int lane = threadIdx.x & 31;
    int w    = threadIdx.x >> 5;
    int row  = blockIdx.x * 8 + w;
    float klp = 0.f;
    if (row < N) {
        size_t off = (size_t)row * 128 + lane * 4;
        float4 m4 = *(const float4*)(MEAN + off);
        float4 l4 = *(const float4*)(LS + off);
        float4 n4 = *(const float4*)(NOISE + off);
        float4 e4 = make_float4(expf(l4.x), expf(l4.y), expf(l4.z), expf(l4.w));
        float4 z4 = make_float4(n4.x * e4.x + m4.x, n4.y * e4.y + m4.y,
                                n4.z * e4.z + m4.z, n4.w * e4.w + m4.w);
        float4 wa = *(const float4*)(Wc + lane * 4);
        float4 wb = *(const float4*)(Wc + 128 + lane * 4);
        float4 wn = *(const float4*)(Wn + lane * 4);
        float up = z4.x * wa.x + z4.y * wa.y + z4.z * wa.z + z4.w * wa.w;
        float vp = z4.x * wb.x + z4.y * wb.y + z4.z * wb.z + z4.w * wb.w;
        float sp = z4.x * wn.x + z4.y * wn.y + z4.z * wn.z + z4.w * wn.w;
        klp = (1.f + 2.f * l4.x - m4.x * m4.x - e4.x * e4.x)
            + (1.f + 2.f * l4.y - m4.y * m4.y - e4.y * e4.y)
            + (1.f + 2.f * l4.z - m4.z * m4.z - e4.z * e4.z)
            + (1.f + 2.f * l4.w - m4.w * m4.w - e4.w * e4.w);
        #pragma unroll
        for (int o = 16; o > 0; o >>= 1) {
            up  += __shfl_xor_sync(0xffffffffu, up,  o);
            vp  += __shfl_xor_sync(0xffffffffu, vp,  o);
            sp  += __shfl_xor_sync(0xffffffffu, sp,  o);
            klp += __shfl_xor_sync(0xffffffffu, klp, o);
        }
        if (lane == 0) {
            g_u[row] = up;
            g_v[row] = vp;
            int b = batch[row];
            atomicAdd(&g_pool[b], sp);
            atomicAdd(&g_cnt[b], 1.0f);
        }
    }
    if (lane == 0) klred[w] = (row < N) ? klp : 0.f;
    __syncthreads();
    if (threadIdx.x == 0) {
        float t = 0.f;
        #pragma unroll
        for (int i = 0; i < 8; i++) t += klred[i];
        atomicAdd(&g_acc[0], t);
    }
}

__global__ void num_k(const float* __restrict__ bridge_num,
                      const float* __restrict__ bnp,
                      float* __restrict__ out_np, int G) {
    __shared__ float red[256];
    int g = blockIdx.x * 256 + threadIdx.x;
    float d = 0.f;
    if (g < G) {
        float np = g_pool[g] / g_cnt[g] + bnp[0];
        out_np[g] = np;
        d = fabsf(np - bridge_num[g]);
    }
    red[threadIdx.x] = d;
    __syncthreads();
    for (int s = 128; s > 0; s >>= 1) {
        if (threadIdx.x < s) red[threadIdx.x] += red[threadIdx.x + s];
        __syncthreads();
    }
    if (threadIdx.x == 0) atomicAdd(&g_acc[1], red[0]);
}

__global__ void apred_k(const int* __restrict__ bidx,
                        const float* __restrict__ bcp,
                        float* __restrict__ out, int P) {
    int p = blockIdx.x * 256 + threadIdx.x;
    if (p >= P) return;
    int i = __ldg(bidx + p);
    int j = __ldg(bidx + P + p);
    float logit = g_u[i] + g_v[j] + bcp[0];
    out[p] = 1.0f / (1.0f + expf(-logit));
}

__global__ void fin_k(float* __restrict__ out, int P, int N, int G) {
    out[P]     = 0.5f * g_acc[0] / ((float)N * (float)N);
    out[P + 1] = g_acc[1] / (float)G;
}

// ---------------------------------------------------------------------------
// Launcher
// ---------------------------------------------------------------------------
extern "C" void kernel_launch(void* const* d_in, const int* in_sizes, int n_in,
                              void* d_out, int out_size) {
    const float* x          = (const float*)d_in[0];
    const int*   ei         = (const int*)  d_in[1];
    const int*   batch      = (const int*)  d_in[2];
    const float* bridge_num = (const float*)d_in[3];
    const int*   bidx       = (const int*)  d_in[4];
    const float* noise      = (const float*)d_in[5];
    const float* W1s        = (const float*)d_in[6];
    const float* b1s        = (const float*)d_in[7];
    const float* gammas     = (const float*)d_in[8];
    const float* betas      = (const float*)d_in[9];
    const float* W2s        = (const float*)d_in[10];
    const float* b2s        = (const float*)d_in[11];
    const float* Wn         = (const float*)d_in[12];
    const float* bnp        = (const float*)d_in[13];
    const float* Wc         = (const float*)d_in[14];
    const float* bcp        = (const float*)d_in[15];
    float* out = (float*)d_out;

    int N = in_sizes[0] / 128;
    int E = in_sizes[1] / 2;
    int G = in_sizes[3];
    int P = in_sizes[4] / 2;

    float *agg, *ht, *h1, *h2, *mean, *ls, *colsum, *colsq, *pool, *cnt, *acc;
    cudaGetSymbolAddress((void**)&agg,    g_agg);
    cudaGetSymbolAddress((void**)&ht,     g_ht);
    cudaGetSymbolAddress((void**)&h1,     g_h1);
    cudaGetSymbolAddress((void**)&h2,     g_h2);
    cudaGetSymbolAddress((void**)&mean,   g_mean);
    cudaGetSymbolAddress((void**)&ls,     g_ls);
    cudaGetSymbolAddress((void**)&colsum, g_colsum);
    cudaGetSymbolAddress((void**)&colsq,  g_colsq);
    cudaGetSymbolAddress((void**)&pool,   g_pool);
    cudaGetSymbolAddress((void**)&cnt,    g_cnt);
    cudaGetSymbolAddress((void**)&acc,    g_acc);

    int rb = (N + BM - 1) / BM;
    int scat_blocks = (E * 32 + 511) / 512;

    // ---- layer 0 ----
    cudaMemsetAsync(agg, 0, (size_t)N * 128 * sizeof(float));
    scatter_k<<<scat_blocks, 512>>>(x, ei, E);
    cudaMemsetAsync(colsum, 0, 512 * sizeof(float));
    cudaMemsetAsync(colsq,  0, 512 * sizeof(float));
    gemm1_k<<<dim3(2, rb), 256>>>(x, W1s, W1s, b1s, ht, N, 256);
    bnfin_k<<<1, 256>>>(gammas, betas, N);
    gemm2_k<<<dim3(1, rb), 256>>>(ht, W2s, b2s, h1, N, 256, 0, 1);

    // ---- layer 1 ----
    cudaMemsetAsync(agg, 0, (size_t)N * 128 * sizeof(float));
    scatter_k<<<scat_blocks, 512>>>(h1, ei, E);
    cudaMemsetAsync(colsum, 0, 512 * sizeof(float));
    cudaMemsetAsync(colsq,  0, 512 * sizeof(float));
    gemm1_k<<<dim3(2, rb), 256>>>(h1, W1s + 1 * 128 * 256, W1s, b1s + 256, ht, N, 256);
    bnfin_k<<<1, 256>>>(gammas + 256, betas + 256, N);
    gemm2_k<<<dim3(1, rb), 256>>>(ht, W2s + 1 * 256 * 128, b2s + 128, h2, N, 256, 0, 1);

    // ---- layers 2+3 combined (shared A = h2 + agg(h2)) ----
    cudaMemsetAsync(agg, 0, (size_t)N * 128 * sizeof(float));
    scatter_k<<<scat_blocks, 512>>>(h2, ei, E);
    cudaMemsetAsync(colsum, 0, 512 * sizeof(float));
    cudaMemsetAsync(colsq,  0, 512 * sizeof(float));
    gemm1_k<<<dim3(4, rb), 256>>>(h2, W1s + 2 * 128 * 256, W1s + 3 * 128 * 256,
                                  b1s + 512, ht, N, 512);
    bnfin_k<<<1, 512>>>(gammas + 512, betas + 512, N);
    gemm2_k<<<dim3(1, rb), 256>>>(ht, W2s + 2 * 256 * 128, b2s + 256, mean, N, 512, 0,   0);
    gemm2_k<<<dim3(1, rb), 256>>>(ht, W2s + 3 * 256 * 128, b2s + 384, ls,   N, 512, 256, 0);

    // ---- epilogue ----
    cudaMemsetAsync(pool, 0, G * sizeof(float));
    cudaMemsetAsync(cnt,  0, G * sizeof(float));
    cudaMemsetAsync(acc,  0, 2 * sizeof(float));
    z_k<<<(N + 7) / 8, 256>>>(mean, ls, noise, batch, Wn, Wc, N);
    num_k<<<(G + 255) / 256, 256>>>(bridge_num, bnp, out + P + 2, G);
    apred_k<<<(P + 255) / 256, 256>>>(bidx, bcp, out, P);
    fin_k<<<1, 1>>>(out, P, N, G);
}